// round 7
// baseline (speedup 1.0000x reference)
#include <cuda_runtime.h>
#include <cuda_bf16.h>
#include <cstdint>

#define THREADS 512
#define LDP 264                      // padded smem row stride (floats): conflict-free

// ---------------- smem byte layout ----------------
#define SM_XS 0                              // X : 40 x 264 f32 = 42240
#define SM_PS (40*LDP*4)                     // P : 64 x 264 f32 = 67584
#define SM_W0 (SM_PS + 64*LDP*4)             // W chunk buf0 (8KB)
#define SM_W1 (SM_W0 + 8192)                 // W chunk buf1 (8KB)
#define SMEM_BYTES (SM_W1 + 8192)            // 126,208 bytes

// ---------------- prepped-W global scratch ----------------
// Per k16-chunk: NT n-tiles x {hi,lo} x 64 b32 words in exact B-fragment
// register order (lane-major, b0/b1 adjacent per lane -> one LDS.b64).
#define NT0 16
#define NT1 16
#define NT2 8
#define CH0 100
#define CH1 160
#define CH2 160
#define CHB0 (NT0*512)       // 8192 B
#define CHB1 (NT1*512)       // 8192 B
#define CHB2 (NT2*512)       // 4096 B
#define OFF0 0u
#define OFF1 (CH0*CHB0)                  // 819200
#define OFF2 (OFF1 + CH1*CHB1)           // 2129920
#define WPRE_BYTES (OFF2 + CH2*CHB2)     // 2785280

__device__ __align__(16) uint8_t g_wpre[WPRE_BYTES];

// ---------------- helpers ----------------
__device__ __forceinline__ uint32_t packb(float lo, float hi) {
    // d<31:16> = cvt(first src), d<15:0> = cvt(second src)
    uint32_t r;
    asm("cvt.rn.bf16x2.f32 %0, %1, %2;" : "=r"(r) : "f"(hi), "f"(lo));
    return r;
}
__device__ __forceinline__ float bf_round(float v) {
    return __bfloat162float(__float2bfloat16(v));
}
__device__ __forceinline__ void mma_bf16(float* c, const uint32_t* a,
                                         uint32_t b0, uint32_t b1) {
    asm volatile(
        "mma.sync.aligned.m16n8k16.row.col.f32.bf16.bf16.f32 "
        "{%0,%1,%2,%3}, {%4,%5,%6,%7}, {%8,%9}, {%0,%1,%2,%3};"
        : "+f"(c[0]), "+f"(c[1]), "+f"(c[2]), "+f"(c[3])
        : "r"(a[0]), "r"(a[1]), "r"(a[2]), "r"(a[3]), "r"(b0), "r"(b1));
}

// ---------------- prep: split W into bf16 hi/lo B-fragment words ----------------
#define WORDS0 (CH0*NT0*128)
#define WORDS1 (CH1*NT1*128)
#define WORDS2 (CH2*NT2*128)

__global__ void prep_kernel(const float* __restrict__ w0,
                            const float* __restrict__ w1,
                            const float* __restrict__ w2)
{
    int i = blockIdx.x * blockDim.x + threadIdx.x;
    if (i >= WORDS0 + WORDS1 + WORDS2) return;
    const float* src; int NT, ld, rowBase, li; uint32_t off, chb;
    if (i < WORDS0)               { src=w0; NT=NT0; ld=1600; rowBase=0;  off=OFF0; chb=CHB0; li=i; }
    else if (i < WORDS0+WORDS1)   { src=w1; NT=NT1; ld=2560; rowBase=0;  off=OFF1; chb=CHB1; li=i-WORDS0; }
    else                          { src=w2; NT=NT2; ld=2560; rowBase=64; off=OFF2; chb=CHB2; li=i-WORDS0-WORDS1; }

    int perChunk = NT * 128;                 // words per chunk
    int c   = li / perChunk;
    int r   = li - c * perChunk;
    int nt  = r >> 7;                        // / 128
    int r2  = r & 127;
    int s   = r2 >> 6;                       // 0=hi, 1=lo
    int fi  = r2 & 63;
    int lane = fi >> 1;
    int wsel = fi & 1;                       // b0 (k+0..1) or b1 (k+8..9)

    int o = nt * 8 + (lane >> 2);
    int k = c * 16 + (lane & 3) * 2 + wsel * 8;
    float a = __ldg(src + (size_t)(rowBase + o) * ld + k);
    float b = __ldg(src + (size_t)(rowBase + o) * ld + k + 1);
    if (s) { a = a - bf_round(a); b = b - bf_round(b); }
    uint32_t w = packb(a, b);                // low half = k element

    *(uint32_t*)(g_wpre + off + (size_t)c * chb
                 + nt * 512 + s * 256 + lane * 8 + wsel * 4) = w;
}

// ---------------- one CIN layer: K-streamed bf16x3 mma.sync GEMM ----------------
template<int NT>
__device__ __forceinline__ void run_layer(
    int nch, const uint8_t* __restrict__ wpre,
    const float* __restrict__ Pp, const float* __restrict__ Xs,
    uint8_t* __restrict__ wb0, uint8_t* __restrict__ wb1,
    float (&acc)[NT][4], int tid, int lane, int q, int tl)
{
    constexpr int CHB = NT * 512;
    constexpr int NG  = NT / 4;              // groups of 4 n-tiles

    #pragma unroll
    for (int nt = 0; nt < NT; ++nt)
        #pragma unroll
        for (int j = 0; j < 4; ++j) acc[nt][j] = 0.0f;

    __syncthreads();   // previous layer's buffer reads / P writes complete

    // prologue: stage chunk 0 into buf0
    {
        const uint4* s = (const uint4*)wpre;
        uint4* d = (uint4*)wb0;
        #pragma unroll 1
        for (int i = tid; i < CHB / 16; i += THREADS) d[i] = s[i];
    }

    #pragma unroll 1
    for (int c = 0; c < nch; ++c) {
        __syncthreads();                       // chunk c staged; buf (c+1)&1 free
        if (c + 1 < nch) {
            const uint4* s = (const uint4*)(wpre + (size_t)(c + 1) * CHB);
            uint4* d = (uint4*)(((c + 1) & 1) ? wb1 : wb0);
            #pragma unroll 1
            for (int i = tid; i < CHB / 16; i += THREADS) d[i] = s[i];
        }
        const uint8_t* __restrict__ wb = (c & 1) ? wb1 : wb0;

        // ---- build A fragments (hi & lo) for this thread's 2 t-rows ----
        const int k0 = c * 16 + q * 2;
        float zl[4], zh[4];
        #pragma unroll
        for (int e = 0; e < 4; ++e) {
            int k = k0 + (e & 1) + (e >> 1) * 8;   // {k0, k0+1, k0+8, k0+9}
            int h = k / 40;
            int m = k - h * 40;
            float pl = Pp[h * LDP + tl];
            float ph = Pp[h * LDP + tl + 8];
            float xl = Xs[m * LDP + tl];
            float xh = Xs[m * LDP + tl + 8];
            zl[e] = pl * xl;
            zh[e] = ph * xh;
        }
        uint32_t ahi[4], alo[4];
        ahi[0] = packb(zl[0], zl[1]);
        ahi[1] = packb(zh[0], zh[1]);
        ahi[2] = packb(zl[2], zl[3]);
        ahi[3] = packb(zh[2], zh[3]);
        alo[0] = packb(zl[0] - bf_round(zl[0]), zl[1] - bf_round(zl[1]));
        alo[1] = packb(zh[0] - bf_round(zh[0]), zh[1] - bf_round(zh[1]));
        alo[2] = packb(zl[2] - bf_round(zl[2]), zl[3] - bf_round(zl[3]));
        alo[3] = packb(zh[2] - bf_round(zh[2]), zh[3] - bf_round(zh[3]));

        // ---- MMAs in groups of 4 n-tiles: same-acc MMAs are 4 issues apart,
        //      per-acc order unchanged (hi*bh, lo*bh, hi*bl) => bit-identical ----
        #pragma unroll
        for (int g = 0; g < NG; ++g) {
            uint2 bh[4], bl[4];
            #pragma unroll
            for (int j = 0; j < 4; ++j) {
                const uint8_t* base = wb + (g * 4 + j) * 512 + lane * 8;
                bh[j] = *(const uint2*)(base);
                bl[j] = *(const uint2*)(base + 256);
            }
            #pragma unroll
            for (int j = 0; j < 4; ++j) mma_bf16(acc[g * 4 + j], ahi, bh[j].x, bh[j].y);
            #pragma unroll
            for (int j = 0; j < 4; ++j) mma_bf16(acc[g * 4 + j], alo, bh[j].x, bh[j].y);
            #pragma unroll
            for (int j = 0; j < 4; ++j) mma_bf16(acc[g * 4 + j], ahi, bl[j].x, bl[j].y);
        }
    }
    __syncthreads();   // all warps done reading smem before epilogue overwrites
}

// ---------------- main kernel ----------------
__global__ void __launch_bounds__(THREADS, 1)
cin_mma_kernel(const float* __restrict__ x,
               const float* __restrict__ b0, const float* __restrict__ b1,
               const float* __restrict__ b2, const float* __restrict__ wl,
               float* __restrict__ out)
{
    extern __shared__ uint8_t smraw[];
    float* Xs = (float*)(smraw + SM_XS);
    float* Ps = (float*)(smraw + SM_PS);
    uint8_t* wb0 = smraw + SM_W0;
    uint8_t* wb1 = smraw + SM_W1;

    const int tid  = threadIdx.x;
    const int warp = tid >> 5;
    const int lane = tid & 31;
    const int q    = lane & 3;        // o-pair / k-pair selector
    const int rr   = lane >> 2;       // row-in-fragment
    const int tl   = warp * 16 + rr;  // this thread's low t-row (high = +8)
    const int bbase = blockIdx.x * 16;

    // X tile: Xs[m][t], t = 16*local_batch + d
    #pragma unroll 1
    for (int i = tid; i < 40 * 256; i += THREADS) {
        int m = i >> 8, t = i & 255;
        Xs[m * LDP + t] = __ldg(x + (size_t)(bbase + (t >> 4)) * 640 + m * 16 + (t & 15));
    }

    float pl = 0.0f, ph = 0.0f;       // direct-feature partials for t=tl, t=tl+8

    // ================= Layer 0: K=1600, P = X =================
    {
        float acc[NT0][4];
        run_layer<NT0>(CH0, g_wpre + OFF0, Xs, Xs, wb0, wb1, acc, tid, lane, q, tl);
        #pragma unroll
        for (int nt = 0; nt < NT0; ++nt) {
            int o = nt * 8 + q * 2;
            float bv0 = __ldg(b0 + o), bv1 = __ldg(b0 + o + 1);
            float v0 = fmaxf(acc[nt][0] + bv0, 0.0f);
            float v1 = fmaxf(acc[nt][1] + bv1, 0.0f);
            float v2 = fmaxf(acc[nt][2] + bv0, 0.0f);
            float v3 = fmaxf(acc[nt][3] + bv1, 0.0f);
            if (nt < 8) {
                Ps[o * LDP + tl]           = v0;
                Ps[(o + 1) * LDP + tl]     = v1;
                Ps[o * LDP + tl + 8]       = v2;
                Ps[(o + 1) * LDP + tl + 8] = v3;
            } else {
                float w0v = __ldg(wl + o - 64), w1v = __ldg(wl + o - 63);
                pl += w0v * v0 + w1v * v1;
                ph += w0v * v2 + w1v * v3;
            }
        }
    }
    // ================= Layer 1: K=2560, P = Ps =================
    {
        float acc[NT1][4];
        run_layer<NT1>(CH1, g_wpre + OFF1, Ps, Xs, wb0, wb1, acc, tid, lane, q, tl);
        #pragma unroll
        for (int nt = 0; nt < NT1; ++nt) {
            int o = nt * 8 + q * 2;
            float bv0 = __ldg(b1 + o), bv1 = __ldg(b1 + o + 1);
            float v0 = fmaxf(acc[nt][0] + bv0, 0.0f);
            float v1 = fmaxf(acc[nt][1] + bv1, 0.0f);
            float v2 = fmaxf(acc[nt][2] + bv0, 0.0f);
            float v3 = fmaxf(acc[nt][3] + bv1, 0.0f);
            if (nt < 8) {
                Ps[o * LDP + tl]           = v0;
                Ps[(o + 1) * LDP + tl]     = v1;
                Ps[o * LDP + tl + 8]       = v2;
                Ps[(o + 1) * LDP + tl + 8] = v3;
            } else {
                float w0v = __ldg(wl + o), w1v = __ldg(wl + o + 1);  // 64 + (o-64)
                pl += w0v * v0 + w1v * v1;
                ph += w0v * v2 + w1v * v3;
            }
        }
    }
    // ========= Layer 2: K=2560, direct half only (N=64) =========
    {
        float acc[NT2][4];
        run_layer<NT2>(CH2, g_wpre + OFF2, Ps, Xs, wb0, wb1, acc, tid, lane, q, tl);
        #pragma unroll
        for (int nt = 0; nt < NT2; ++nt) {
            int o = nt * 8 + q * 2;                  // channel-in-half 0..63
            float bv0 = __ldg(b2 + 64 + o), bv1 = __ldg(b2 + 65 + o);
            float v0 = fmaxf(acc[nt][0] + bv0, 0.0f);
            float v1 = fmaxf(acc[nt][1] + bv1, 0.0f);
            float v2 = fmaxf(acc[nt][2] + bv0, 0.0f);
            float v3 = fmaxf(acc[nt][3] + bv1, 0.0f);
            float w0v = __ldg(wl + 128 + o), w1v = __ldg(wl + 129 + o);
            pl += w0v * v0 + w1v * v1;
            ph += w0v * v2 + w1v * v3;
        }
    }

    // ---- per-batch reduction: warp == batch, sum over its 16 t's ----
    float p = pl + ph;
    #pragma unroll
    for (int off = 16; off >= 1; off >>= 1)
        p += __shfl_xor_sync(0xffffffffu, p, off);
    if (lane == 0) out[bbase + warp] = p;
}

extern "C" void kernel_launch(void* const* d_in, const int* in_sizes, int n_in,
                              void* d_out, int out_size)
{
    const float* x  = (const float*)d_in[0];
    const float* w0 = (const float*)d_in[1];
    const float* b0 = (const float*)d_in[2];
    const float* w1 = (const float*)d_in[3];
    const float* b1 = (const float*)d_in[4];
    const float* w2 = (const float*)d_in[5];
    const float* b2 = (const float*)d_in[6];
    const float* wl = (const float*)d_in[7];
    float* out = (float*)d_out;

    int prepN = WORDS0 + WORDS1 + WORDS2;
    prep_kernel<<<(prepN + 255) / 256, 256>>>(w0, w1, w2);

    cudaFuncSetAttribute(cin_mma_kernel,
                         cudaFuncAttributeMaxDynamicSharedMemorySize, SMEM_BYTES);
    cin_mma_kernel<<<128, THREADS, SMEM_BYTES>>>(x, b0, b1, b2, wl, out);
}

// round 8
// speedup vs baseline: 1.1162x; 1.1162x over previous
#include <cuda_runtime.h>
#include <cuda_bf16.h>
#include <cstdint>

#define THREADS 256
#define NB 8                          // batches per CTA
#define LDP 136                       // padded smem row stride (floats)

// ---------------- smem byte layout ----------------
#define SM_XS 0                              // X : 40 x 136 f32 = 21760
#define SM_PS (40*LDP*4)                     // P : 64 x 136 f32 = 34816
#define SM_W0 (SM_PS + 64*LDP*4)             // W chunk buf0 (8KB)
#define SM_W1 (SM_W0 + 8192)                 // W chunk buf1 (8KB)
#define SMEM_BYTES (SM_W1 + 8192)            // 72,960 bytes -> 2 CTAs/SM

// ---------------- prepped-W global scratch ----------------
// Per k16-chunk: NT n-tiles x {hi,lo} x 64 b32 words in exact B-fragment
// register order (lane-major, b0/b1 adjacent per lane -> one LDS.b64).
#define NT0 16
#define NT1 16
#define NT2 8
#define CH0 100
#define CH1 160
#define CH2 160
#define CHB0 (NT0*512)       // 8192 B
#define CHB1 (NT1*512)       // 8192 B
#define CHB2 (NT2*512)       // 4096 B
#define OFF0 0u
#define OFF1 (CH0*CHB0)                  // 819200
#define OFF2 (OFF1 + CH1*CHB1)           // 2129920
#define WPRE_BYTES (OFF2 + CH2*CHB2)     // 2785280

__device__ __align__(16) uint8_t g_wpre[WPRE_BYTES];

// ---------------- helpers ----------------
__device__ __forceinline__ uint32_t packb(float lo, float hi) {
    uint32_t r;
    asm("cvt.rn.bf16x2.f32 %0, %1, %2;" : "=r"(r) : "f"(hi), "f"(lo));
    return r;
}
__device__ __forceinline__ float bf_round(float v) {
    return __bfloat162float(__float2bfloat16(v));
}
__device__ __forceinline__ void mma_bf16(float* c, const uint32_t* a,
                                         uint32_t b0, uint32_t b1) {
    asm volatile(
        "mma.sync.aligned.m16n8k16.row.col.f32.bf16.bf16.f32 "
        "{%0,%1,%2,%3}, {%4,%5,%6,%7}, {%8,%9}, {%0,%1,%2,%3};"
        : "+f"(c[0]), "+f"(c[1]), "+f"(c[2]), "+f"(c[3])
        : "r"(a[0]), "r"(a[1]), "r"(a[2]), "r"(a[3]), "r"(b0), "r"(b1));
}

// ---------------- prep: split W into bf16 hi/lo B-fragment words ----------------
#define WORDS0 (CH0*NT0*128)
#define WORDS1 (CH1*NT1*128)
#define WORDS2 (CH2*NT2*128)

__global__ void prep_kernel(const float* __restrict__ w0,
                            const float* __restrict__ w1,
                            const float* __restrict__ w2)
{
    int i = blockIdx.x * blockDim.x + threadIdx.x;
    if (i >= WORDS0 + WORDS1 + WORDS2) return;
    const float* src; int NT, ld, rowBase, li; uint32_t off, chb;
    if (i < WORDS0)               { src=w0; NT=NT0; ld=1600; rowBase=0;  off=OFF0; chb=CHB0; li=i; }
    else if (i < WORDS0+WORDS1)   { src=w1; NT=NT1; ld=2560; rowBase=0;  off=OFF1; chb=CHB1; li=i-WORDS0; }
    else                          { src=w2; NT=NT2; ld=2560; rowBase=64; off=OFF2; chb=CHB2; li=i-WORDS0-WORDS1; }

    int perChunk = NT * 128;
    int c   = li / perChunk;
    int r   = li - c * perChunk;
    int nt  = r >> 7;
    int r2  = r & 127;
    int s   = r2 >> 6;                       // 0=hi, 1=lo
    int fi  = r2 & 63;
    int lane = fi >> 1;
    int wsel = fi & 1;                       // b0 (k+0..1) or b1 (k+8..9)

    int o = nt * 8 + (lane >> 2);
    int k = c * 16 + (lane & 3) * 2 + wsel * 8;
    float a = __ldg(src + (size_t)(rowBase + o) * ld + k);
    float b = __ldg(src + (size_t)(rowBase + o) * ld + k + 1);
    if (s) { a = a - bf_round(a); b = b - bf_round(b); }
    uint32_t w = packb(a, b);

    *(uint32_t*)(g_wpre + off + (size_t)c * chb
                 + nt * 512 + s * 256 + lane * 8 + wsel * 4) = w;
}

// ---------------- one CIN layer: K-streamed bf16x3 mma.sync GEMM ----------------
template<int NT>
__device__ __forceinline__ void run_layer(
    int nch, const uint8_t* __restrict__ wpre,
    const float* __restrict__ Pp, const float* __restrict__ Xs,
    uint8_t* __restrict__ wb0, uint8_t* __restrict__ wb1,
    float (&acc)[NT][4], int tid, int lane, int q, int tl)
{
    constexpr int CHB = NT * 512;
    constexpr int NG  = NT / 4;

    #pragma unroll
    for (int nt = 0; nt < NT; ++nt)
        #pragma unroll
        for (int j = 0; j < 4; ++j) acc[nt][j] = 0.0f;

    __syncthreads();   // previous layer's buffer reads / P writes complete

    // prologue: stage chunk 0 into buf0
    {
        const uint4* s = (const uint4*)wpre;
        uint4* d = (uint4*)wb0;
        #pragma unroll 1
        for (int i = tid; i < CHB / 16; i += THREADS) d[i] = s[i];
    }

    #pragma unroll 1
    for (int c = 0; c < nch; ++c) {
        __syncthreads();                       // chunk c staged; buf (c+1)&1 free
        if (c + 1 < nch) {
            const uint4* s = (const uint4*)(wpre + (size_t)(c + 1) * CHB);
            uint4* d = (uint4*)(((c + 1) & 1) ? wb1 : wb0);
            #pragma unroll 1
            for (int i = tid; i < CHB / 16; i += THREADS) d[i] = s[i];
        }
        const uint8_t* __restrict__ wb = (c & 1) ? wb1 : wb0;

        // ---- build A fragments (hi & lo) for this thread's 2 t-rows ----
        const int k0 = c * 16 + q * 2;
        float zl[4], zh[4];
        #pragma unroll
        for (int e = 0; e < 4; ++e) {
            int k = k0 + (e & 1) + (e >> 1) * 8;   // {k0, k0+1, k0+8, k0+9}
            int h = k / 40;
            int m = k - h * 40;
            float pv0 = Pp[h * LDP + tl];
            float pv1 = Pp[h * LDP + tl + 8];
            float xv0 = Xs[m * LDP + tl];
            float xv1 = Xs[m * LDP + tl + 8];
            zl[e] = pv0 * xv0;
            zh[e] = pv1 * xv1;
        }
        uint32_t ahi[4], alo[4];
        ahi[0] = packb(zl[0], zl[1]);
        ahi[1] = packb(zh[0], zh[1]);
        ahi[2] = packb(zl[2], zl[3]);
        ahi[3] = packb(zh[2], zh[3]);
        alo[0] = packb(zl[0] - bf_round(zl[0]), zl[1] - bf_round(zl[1]));
        alo[1] = packb(zh[0] - bf_round(zh[0]), zh[1] - bf_round(zh[1]));
        alo[2] = packb(zl[2] - bf_round(zl[2]), zl[3] - bf_round(zl[3]));
        alo[3] = packb(zh[2] - bf_round(zh[2]), zh[3] - bf_round(zh[3]));

        // ---- MMAs in groups of 4 n-tiles ----
        #pragma unroll
        for (int g = 0; g < NG; ++g) {
            uint2 bh[4], bl[4];
            #pragma unroll
            for (int j = 0; j < 4; ++j) {
                const uint8_t* base = wb + (g * 4 + j) * 512 + lane * 8;
                bh[j] = *(const uint2*)(base);
                bl[j] = *(const uint2*)(base + 256);
            }
            #pragma unroll
            for (int j = 0; j < 4; ++j) mma_bf16(acc[g * 4 + j], ahi, bh[j].x, bh[j].y);
            #pragma unroll
            for (int j = 0; j < 4; ++j) mma_bf16(acc[g * 4 + j], alo, bh[j].x, bh[j].y);
            #pragma unroll
            for (int j = 0; j < 4; ++j) mma_bf16(acc[g * 4 + j], ahi, bl[j].x, bl[j].y);
        }
    }
    __syncthreads();   // all warps done reading smem before epilogue overwrites
}

// ---------------- main kernel ----------------
__global__ void __launch_bounds__(THREADS, 2)
cin_mma_kernel(const float* __restrict__ x,
               const float* __restrict__ b0, const float* __restrict__ b1,
               const float* __restrict__ b2, const float* __restrict__ wl,
               float* __restrict__ out)
{
    extern __shared__ uint8_t smraw[];
    float* Xs = (float*)(smraw + SM_XS);
    float* Ps = (float*)(smraw + SM_PS);
    uint8_t* wb0 = smraw + SM_W0;
    uint8_t* wb1 = smraw + SM_W1;

    const int tid  = threadIdx.x;
    const int warp = tid >> 5;        // warp == local batch (0..7)
    const int lane = tid & 31;
    const int q    = lane & 3;        // o-pair / k-pair selector
    const int rr   = lane >> 2;       // row-in-fragment
    const int tl   = warp * 16 + rr;  // this thread's low t-row (high = +8)
    const int bbase = blockIdx.x * NB;

    // X tile: Xs[m][t], t = 16*local_batch + d   (40*128 elems)
    #pragma unroll 1
    for (int i = tid; i < 40 * 128; i += THREADS) {
        int m = i >> 7, t = i & 127;
        Xs[m * LDP + t] = __ldg(x + (size_t)(bbase + (t >> 4)) * 640 + m * 16 + (t & 15));
    }

    float pl = 0.0f, ph = 0.0f;       // direct-feature partials for t=tl, t=tl+8

    // ================= Layer 0: K=1600, P = X =================
    {
        float acc[NT0][4];
        run_layer<NT0>(CH0, g_wpre + OFF0, Xs, Xs, wb0, wb1, acc, tid, lane, q, tl);
        #pragma unroll
        for (int nt = 0; nt < NT0; ++nt) {
            int o = nt * 8 + q * 2;
            float bv0 = __ldg(b0 + o), bv1 = __ldg(b0 + o + 1);
            float v0 = fmaxf(acc[nt][0] + bv0, 0.0f);
            float v1 = fmaxf(acc[nt][1] + bv1, 0.0f);
            float v2 = fmaxf(acc[nt][2] + bv0, 0.0f);
            float v3 = fmaxf(acc[nt][3] + bv1, 0.0f);
            if (nt < 8) {
                Ps[o * LDP + tl]           = v0;
                Ps[(o + 1) * LDP + tl]     = v1;
                Ps[o * LDP + tl + 8]       = v2;
                Ps[(o + 1) * LDP + tl + 8] = v3;
            } else {
                float w0v = __ldg(wl + o - 64), w1v = __ldg(wl + o - 63);
                pl += w0v * v0 + w1v * v1;
                ph += w0v * v2 + w1v * v3;
            }
        }
    }
    // ================= Layer 1: K=2560, P = Ps =================
    {
        float acc[NT1][4];
        run_layer<NT1>(CH1, g_wpre + OFF1, Ps, Xs, wb0, wb1, acc, tid, lane, q, tl);
        #pragma unroll
        for (int nt = 0; nt < NT1; ++nt) {
            int o = nt * 8 + q * 2;
            float bv0 = __ldg(b1 + o), bv1 = __ldg(b1 + o + 1);
            float v0 = fmaxf(acc[nt][0] + bv0, 0.0f);
            float v1 = fmaxf(acc[nt][1] + bv1, 0.0f);
            float v2 = fmaxf(acc[nt][2] + bv0, 0.0f);
            float v3 = fmaxf(acc[nt][3] + bv1, 0.0f);
            if (nt < 8) {
                Ps[o * LDP + tl]           = v0;
                Ps[(o + 1) * LDP + tl]     = v1;
                Ps[o * LDP + tl + 8]       = v2;
                Ps[(o + 1) * LDP + tl + 8] = v3;
            } else {
                float w0v = __ldg(wl + o), w1v = __ldg(wl + o + 1);  // 64 + (o-64)
                pl += w0v * v0 + w1v * v1;
                ph += w0v * v2 + w1v * v3;
            }
        }
    }
    // ========= Layer 2: K=2560, direct half only (N=64) =========
    {
        float acc[NT2][4];
        run_layer<NT2>(CH2, g_wpre + OFF2, Ps, Xs, wb0, wb1, acc, tid, lane, q, tl);
        #pragma unroll
        for (int nt = 0; nt < NT2; ++nt) {
            int o = nt * 8 + q * 2;                  // channel-in-half 0..63
            float bv0 = __ldg(b2 + 64 + o), bv1 = __ldg(b2 + 65 + o);
            float v0 = fmaxf(acc[nt][0] + bv0, 0.0f);
            float v1 = fmaxf(acc[nt][1] + bv1, 0.0f);
            float v2 = fmaxf(acc[nt][2] + bv0, 0.0f);
            float v3 = fmaxf(acc[nt][3] + bv1, 0.0f);
            float w0v = __ldg(wl + 128 + o), w1v = __ldg(wl + 129 + o);
            pl += w0v * v0 + w1v * v1;
            ph += w0v * v2 + w1v * v3;
        }
    }

    // ---- per-batch reduction: warp == batch, sum over its 16 t's ----
    float p = pl + ph;
    #pragma unroll
    for (int off = 16; off >= 1; off >>= 1)
        p += __shfl_xor_sync(0xffffffffu, p, off);
    if (lane == 0) out[bbase + warp] = p;
}

extern "C" void kernel_launch(void* const* d_in, const int* in_sizes, int n_in,
                              void* d_out, int out_size)
{
    const float* x  = (const float*)d_in[0];
    const float* w0 = (const float*)d_in[1];
    const float* b0 = (const float*)d_in[2];
    const float* w1 = (const float*)d_in[3];
    const float* b1 = (const float*)d_in[4];
    const float* w2 = (const float*)d_in[5];
    const float* b2 = (const float*)d_in[6];
    const float* wl = (const float*)d_in[7];
    float* out = (float*)d_out;

    int prepN = WORDS0 + WORDS1 + WORDS2;
    prep_kernel<<<(prepN + 255) / 256, 256>>>(w0, w1, w2);

    cudaFuncSetAttribute(cin_mma_kernel,
                         cudaFuncAttributeMaxDynamicSharedMemorySize, SMEM_BYTES);
    cin_mma_kernel<<<2048 / NB, THREADS, SMEM_BYTES>>>(x, b0, b1, b2, wl, out);
}

// round 9
// speedup vs baseline: 1.2117x; 1.0855x over previous
#include <cuda_runtime.h>
#include <cuda_bf16.h>
#include <cstdint>

#define THREADS 256
#define NB 8                          // batches per CTA
#define LDP 136                       // padded smem row stride (floats)

// ---------------- smem byte layout ----------------
#define SM_XS 0                              // X : 40 x 136 f32 = 21760
#define SM_PS (40*LDP*4)                     // P : 64 x 136 f32 = 34816
#define SM_W0 (SM_PS + 64*LDP*4)             // W chunk32 buf0 (16KB)
#define SM_W1 (SM_W0 + 16384)                // W chunk32 buf1 (16KB)
#define SMEM_BYTES (SM_W1 + 16384)           // 89,344 bytes -> 2 CTAs/SM

// ---------------- prepped-W global scratch ----------------
// K=32 chunks. Per chunk: [s2=0|1 k16-step] x [NT/2 tile-pairs] x [hi|lo] blocks.
// Block = 32 lanes x 16B: per lane {tile2p.b0, tile2p.b1, tile2p+1.b0, tile2p+1.b1}
// -> one conflict-free ld.shared.v4 per 2 tiles.
#define NT0 16
#define NT1 16
#define NT2 8
#define CH0 50
#define CH1 80
#define CH2 80
#define CHB0 (NT0*1024)      // 16384 B per chunk32
#define CHB1 (NT1*1024)      // 16384 B
#define CHB2 (NT2*1024)      // 8192 B
#define OFF0 0u
#define OFF1 (CH0*CHB0)                  // 819200
#define OFF2 (OFF1 + CH1*CHB1)           // 2129920
#define WPRE_BYTES (OFF2 + CH2*CHB2)     // 2785280

__device__ __align__(16) uint8_t g_wpre[WPRE_BYTES];

// ---------------- helpers ----------------
__device__ __forceinline__ uint32_t packb(float lo, float hi) {
    uint32_t r;
    asm("cvt.rn.bf16x2.f32 %0, %1, %2;" : "=r"(r) : "f"(hi), "f"(lo));
    return r;
}
__device__ __forceinline__ float bf_round(float v) {
    return __bfloat162float(__float2bfloat16(v));
}
__device__ __forceinline__ void mma_bf16(float* c, const uint32_t* a,
                                         uint32_t b0, uint32_t b1) {
    asm volatile(
        "mma.sync.aligned.m16n8k16.row.col.f32.bf16.bf16.f32 "
        "{%0,%1,%2,%3}, {%4,%5,%6,%7}, {%8,%9}, {%0,%1,%2,%3};"
        : "+f"(c[0]), "+f"(c[1]), "+f"(c[2]), "+f"(c[3])
        : "r"(a[0]), "r"(a[1]), "r"(a[2]), "r"(a[3]), "r"(b0), "r"(b1));
}
__device__ __forceinline__ uint32_t smem_u32(const void* p) {
    uint32_t a;
    asm("{ .reg .u64 t; cvta.to.shared.u64 t, %1; cvt.u32.u64 %0, t; }" : "=r"(a) : "l"(p));
    return a;
}
__device__ __forceinline__ void cp_async16(uint32_t dst, const void* src) {
    asm volatile("cp.async.cg.shared.global [%0], [%1], 16;" :: "r"(dst), "l"(src));
}
#define CP_COMMIT() asm volatile("cp.async.commit_group;" ::: "memory")
#define CP_WAIT0()  asm volatile("cp.async.wait_group 0;" ::: "memory")

// ---------------- prep: split W into paired bf16 hi/lo B-fragment blocks ----------------
#define WORDS0 (CH0*NT0*256)   // 204800
#define WORDS1 (CH1*NT1*256)   // 327680
#define WORDS2 (CH2*NT2*256)   // 163840

__global__ void prep_kernel(const float* __restrict__ w0,
                            const float* __restrict__ w1,
                            const float* __restrict__ w2)
{
    int i = blockIdx.x * blockDim.x + threadIdx.x;
    if (i >= WORDS0 + WORDS1 + WORDS2) return;
    const float* src; int NT, ld, rowBase, li; uint32_t off, chb;
    if (i < WORDS0)               { src=w0; NT=NT0; ld=1600; rowBase=0;  off=OFF0; chb=CHB0; li=i; }
    else if (i < WORDS0+WORDS1)   { src=w1; NT=NT1; ld=2560; rowBase=0;  off=OFF1; chb=CHB1; li=i-WORDS0; }
    else                          { src=w2; NT=NT2; ld=2560; rowBase=64; off=OFF2; chb=CHB2; li=i-WORDS0-WORDS1; }

    int perChunk = NT * 256;                  // b32 words per chunk32
    int c    = li / perChunk;
    int r    = li - c * perChunk;
    int half = NT * 128;                      // words per k16-step
    int s2   = r / half;
    int r2   = r - s2 * half;
    int pair = r2 >> 8;                       // / 256
    int r3   = r2 & 255;
    int sel  = r3 >> 7;                       // 0=hi, 1=lo
    int r4   = r3 & 127;
    int lane = r4 >> 2;
    int w4   = r4 & 3;                        // word within 16B
    int tile = pair * 2 + (w4 >> 1);
    int wsel = w4 & 1;                        // b0 (k+0..1) or b1 (k+8..9)

    int o = tile * 8 + (lane >> 2);
    int k = c * 32 + s2 * 16 + (lane & 3) * 2 + wsel * 8;
    float a = __ldg(src + (size_t)(rowBase + o) * ld + k);
    float b = __ldg(src + (size_t)(rowBase + o) * ld + k + 1);
    if (sel) { a = a - bf_round(a); b = b - bf_round(b); }
    uint32_t w = packb(a, b);                 // low half = k element

    *(uint32_t*)(g_wpre + off + (size_t)c * chb
                 + s2 * (uint32_t)(NT / 2) * 1024 + pair * 1024 + sel * 512
                 + lane * 16 + w4 * 4) = w;
}

// ---------------- one CIN layer: K32-streamed bf16x3 mma.sync GEMM ----------------
template<int NT>
__device__ __forceinline__ void run_layer(
    int nch, const uint8_t* __restrict__ wpre,
    const float* __restrict__ Pp, const float* __restrict__ Xs,
    const uint8_t* __restrict__ wb0, const uint8_t* __restrict__ wb1,
    uint32_t wb0u, uint32_t wb1u,
    float (&acc)[NT][4], int tid, int lane, int q, int tl)
{
    constexpr int CHB = NT * 1024;
    constexpr int NP  = NT / 2;               // tile pairs per k16-step
    constexpr int NG  = NT / 4;               // 4-tile groups
    constexpr int CPT = CHB / 16 / THREADS;   // cp.async16 per thread (4 or 2)

    #pragma unroll
    for (int nt = 0; nt < NT; ++nt)
        #pragma unroll
        for (int j = 0; j < 4; ++j) acc[nt][j] = 0.0f;

    __syncthreads();   // previous layer's buffer reads / P writes complete

    // prologue: async-stage chunk 0 into buf0
    #pragma unroll
    for (int i = 0; i < CPT; ++i) {
        int e = tid + i * THREADS;
        cp_async16(wb0u + e * 16, wpre + e * 16);
    }
    CP_COMMIT();

    #pragma unroll 1
    for (int c = 0; c < nch; ++c) {
        CP_WAIT0();
        __syncthreads();                      // chunk c visible to all; prev reads done
        if (c + 1 < nch) {
            const uint8_t* src = wpre + (size_t)(c + 1) * CHB;
            uint32_t dst = ((c + 1) & 1) ? wb1u : wb0u;
            #pragma unroll
            for (int i = 0; i < CPT; ++i) {
                int e = tid + i * THREADS;
                cp_async16(dst + e * 16, src + e * 16);
            }
        }
        CP_COMMIT();                          // overlaps with compute below
        const uint8_t* __restrict__ wb = (c & 1) ? wb1 : wb0;

        #pragma unroll
        for (int s2 = 0; s2 < 2; ++s2) {
            // ---- build A fragments (hi & lo) for this thread's 2 t-rows ----
            const int k0 = c * 32 + s2 * 16 + q * 2;
            float zl[4], zh[4];
            #pragma unroll
            for (int e = 0; e < 4; ++e) {
                int k = k0 + (e & 1) + (e >> 1) * 8;   // {k0, k0+1, k0+8, k0+9}
                int h = k / 40;
                int m = k - h * 40;
                float pv0 = Pp[h * LDP + tl];
                float pv1 = Pp[h * LDP + tl + 8];
                float xv0 = Xs[m * LDP + tl];
                float xv1 = Xs[m * LDP + tl + 8];
                zl[e] = pv0 * xv0;
                zh[e] = pv1 * xv1;
            }
            uint32_t ahi[4], alo[4];
            ahi[0] = packb(zl[0], zl[1]);
            ahi[1] = packb(zh[0], zh[1]);
            ahi[2] = packb(zl[2], zl[3]);
            ahi[3] = packb(zh[2], zh[3]);
            alo[0] = packb(zl[0] - bf_round(zl[0]), zl[1] - bf_round(zl[1]));
            alo[1] = packb(zh[0] - bf_round(zh[0]), zh[1] - bf_round(zh[1]));
            alo[2] = packb(zl[2] - bf_round(zl[2]), zl[3] - bf_round(zl[3]));
            alo[3] = packb(zh[2] - bf_round(zh[2]), zh[3] - bf_round(zh[3]));

            const uint8_t* __restrict__ wbs = wb + s2 * (NP * 1024) ;

            // ---- 4 tiles per group, per-acc order hi*bh, lo*bh, hi*bl ----
            #pragma unroll
            for (int g = 0; g < NG; ++g) {
                const uint4 h0 = *(const uint4*)(wbs + (2 * g    ) * 1024 + lane * 16);
                const uint4 h1 = *(const uint4*)(wbs + (2 * g + 1) * 1024 + lane * 16);
                const uint4 l0 = *(const uint4*)(wbs + (2 * g    ) * 1024 + 512 + lane * 16);
                const uint4 l1 = *(const uint4*)(wbs + (2 * g + 1) * 1024 + 512 + lane * 16);
                mma_bf16(acc[4 * g + 0], ahi, h0.x, h0.y);
                mma_bf16(acc[4 * g + 1], ahi, h0.z, h0.w);
                mma_bf16(acc[4 * g + 2], ahi, h1.x, h1.y);
                mma_bf16(acc[4 * g + 3], ahi, h1.z, h1.w);
                mma_bf16(acc[4 * g + 0], alo, h0.x, h0.y);
                mma_bf16(acc[4 * g + 1], alo, h0.z, h0.w);
                mma_bf16(acc[4 * g + 2], alo, h1.x, h1.y);
                mma_bf16(acc[4 * g + 3], alo, h1.z, h1.w);
                mma_bf16(acc[4 * g + 0], ahi, l0.x, l0.y);
                mma_bf16(acc[4 * g + 1], ahi, l0.z, l0.w);
                mma_bf16(acc[4 * g + 2], ahi, l1.x, l1.y);
                mma_bf16(acc[4 * g + 3], ahi, l1.z, l1.w);
            }
        }
    }
    __syncthreads();   // all warps done reading smem before epilogue overwrites
}

// ---------------- main kernel ----------------
__global__ void __launch_bounds__(THREADS, 2)
cin_mma_kernel(const float* __restrict__ x,
               const float* __restrict__ b0, const float* __restrict__ b1,
               const float* __restrict__ b2, const float* __restrict__ wl,
               float* __restrict__ out)
{
    extern __shared__ uint8_t smraw[];
    float* Xs = (float*)(smraw + SM_XS);
    float* Ps = (float*)(smraw + SM_PS);
    uint8_t* wb0 = smraw + SM_W0;
    uint8_t* wb1 = smraw + SM_W1;
    const uint32_t wb0u = smem_u32(wb0);
    const uint32_t wb1u = smem_u32(wb1);

    const int tid  = threadIdx.x;
    const int warp = tid >> 5;        // warp == local batch (0..7)
    const int lane = tid & 31;
    const int q    = lane & 3;        // o-pair / k-pair selector
    const int rr   = lane >> 2;       // row-in-fragment
    const int tl   = warp * 16 + rr;  // this thread's low t-row (high = +8)
    const int bbase = blockIdx.x * NB;

    // X tile: Xs[m][t], t = 16*local_batch + d   (40*128 elems)
    #pragma unroll 1
    for (int i = tid; i < 40 * 128; i += THREADS) {
        int m = i >> 7, t = i & 127;
        Xs[m * LDP + t] = __ldg(x + (size_t)(bbase + (t >> 4)) * 640 + m * 16 + (t & 15));
    }

    float pl = 0.0f, ph = 0.0f;       // direct-feature partials for t=tl, t=tl+8

    // ================= Layer 0: K=1600, P = X =================
    {
        float acc[NT0][4];
        run_layer<NT0>(CH0, g_wpre + OFF0, Xs, Xs, wb0, wb1, wb0u, wb1u,
                       acc, tid, lane, q, tl);
        #pragma unroll
        for (int nt = 0; nt < NT0; ++nt) {
            int o = nt * 8 + q * 2;
            float bv0 = __ldg(b0 + o), bv1 = __ldg(b0 + o + 1);
            float v0 = fmaxf(acc[nt][0] + bv0, 0.0f);
            float v1 = fmaxf(acc[nt][1] + bv1, 0.0f);
            float v2 = fmaxf(acc[nt][2] + bv0, 0.0f);
            float v3 = fmaxf(acc[nt][3] + bv1, 0.0f);
            if (nt < 8) {
                Ps[o * LDP + tl]           = v0;
                Ps[(o + 1) * LDP + tl]     = v1;
                Ps[o * LDP + tl + 8]       = v2;
                Ps[(o + 1) * LDP + tl + 8] = v3;
            } else {
                float w0v = __ldg(wl + o - 64), w1v = __ldg(wl + o - 63);
                pl += w0v * v0 + w1v * v1;
                ph += w0v * v2 + w1v * v3;
            }
        }
    }
    // ================= Layer 1: K=2560, P = Ps =================
    {
        float acc[NT1][4];
        run_layer<NT1>(CH1, g_wpre + OFF1, Ps, Xs, wb0, wb1, wb0u, wb1u,
                       acc, tid, lane, q, tl);
        #pragma unroll
        for (int nt = 0; nt < NT1; ++nt) {
            int o = nt * 8 + q * 2;
            float bv0 = __ldg(b1 + o), bv1 = __ldg(b1 + o + 1);
            float v0 = fmaxf(acc[nt][0] + bv0, 0.0f);
            float v1 = fmaxf(acc[nt][1] + bv1, 0.0f);
            float v2 = fmaxf(acc[nt][2] + bv0, 0.0f);
            float v3 = fmaxf(acc[nt][3] + bv1, 0.0f);
            if (nt < 8) {
                Ps[o * LDP + tl]           = v0;
                Ps[(o + 1) * LDP + tl]     = v1;
                Ps[o * LDP + tl + 8]       = v2;
                Ps[(o + 1) * LDP + tl + 8] = v3;
            } else {
                float w0v = __ldg(wl + o), w1v = __ldg(wl + o + 1);  // 64 + (o-64)
                pl += w0v * v0 + w1v * v1;
                ph += w0v * v2 + w1v * v3;
            }
        }
    }
    // ========= Layer 2: K=2560, direct half only (N=64) =========
    {
        float acc[NT2][4];
        run_layer<NT2>(CH2, g_wpre + OFF2, Ps, Xs, wb0, wb1, wb0u, wb1u,
                       acc, tid, lane, q, tl);
        #pragma unroll
        for (int nt = 0; nt < NT2; ++nt) {
            int o = nt * 8 + q * 2;                  // channel-in-half 0..63
            float bv0 = __ldg(b2 + 64 + o), bv1 = __ldg(b2 + 65 + o);
            float v0 = fmaxf(acc[nt][0] + bv0, 0.0f);
            float v1 = fmaxf(acc[nt][1] + bv1, 0.0f);
            float v2 = fmaxf(acc[nt][2] + bv0, 0.0f);
            float v3 = fmaxf(acc[nt][3] + bv1, 0.0f);
            float w0v = __ldg(wl + 128 + o), w1v = __ldg(wl + 129 + o);
            pl += w0v * v0 + w1v * v1;
            ph += w0v * v2 + w1v * v3;
        }
    }

    // ---- per-batch reduction: warp == batch, sum over its 16 t's ----
    float p = pl + ph;
    #pragma unroll
    for (int off = 16; off >= 1; off >>= 1)
        p += __shfl_xor_sync(0xffffffffu, p, off);
    if (lane == 0) out[bbase + warp] = p;
}

extern "C" void kernel_launch(void* const* d_in, const int* in_sizes, int n_in,
                              void* d_out, int out_size)
{
    const float* x  = (const float*)d_in[0];
    const float* w0 = (const float*)d_in[1];
    const float* b0 = (const float*)d_in[2];
    const float* w1 = (const float*)d_in[3];
    const float* b1 = (const float*)d_in[4];
    const float* w2 = (const float*)d_in[5];
    const float* b2 = (const float*)d_in[6];
    const float* wl = (const float*)d_in[7];
    float* out = (float*)d_out;

    int prepN = WORDS0 + WORDS1 + WORDS2;
    prep_kernel<<<(prepN + 255) / 256, 256>>>(w0, w1, w2);

    cudaFuncSetAttribute(cin_mma_kernel,
                         cudaFuncAttributeMaxDynamicSharedMemorySize, SMEM_BYTES);
    cin_mma_kernel<<<2048 / NB, THREADS, SMEM_BYTES>>>(x, b0, b1, b2, wl, out);
}